// round 5
// baseline (speedup 1.0000x reference)
#include <cuda_runtime.h>
#include <cstdint>

#define Bb 4
#define Mm 256
#define Tt 64
#define BT 256      // B*T
#define KD 512      // 2M == D_MOT == D_ABS
#define DOUT 768
#define JSPLIT 4
#define KSPLIT 2
#define PSZ (3*BT*KD)   // one stage1 partial plane (768 x 512)

// Scratch (no allocation allowed -> __device__ globals)
__device__ float d_V [Mm*BT];              // V [j][bt]
__device__ float d_VX[Mm*BT];
__device__ float d_VY[Mm*BT];
__device__ float d_S1p[JSPLIT*PSZ];        // stage1 partials
__device__ float d_cvp[KSPLIT*DOUT];       // cvec partials (fcoutb folded into plane 0)
__device__ float d_S2p[KSPLIT*1024*DOUT];  // stage2 partials (rows 0..767 A, 768..1023 base)

__device__ __forceinline__ bool is_nan_bits(float x) {
    return (__float_as_uint(x) & 0x7fffffffu) > 0x7f800000u;
}

// ---------------------------------------------------------------------------
// prep: build V/VX/VY in (j, bt) layout.  grid=(256 j), block=256 (bt)
// ---------------------------------------------------------------------------
__global__ void prep_kernel(const float* __restrict__ coords,
                            const float* __restrict__ vis) {
    int j = blockIdx.x;
    int t = threadIdx.x;           // bt = b*64 + tt
    int b = t >> 6, tt = t & 63;
    int idx = (b*Mm + j)*Tt + tt;
    float2 xy = ((const float2*)coords)[idx];
    float v = vis[idx];
    float x = xy.x, y = xy.y;
    if (is_nan_bits(x)) { v = 0.f; x = 0.f; }
    if (is_nan_bits(y)) { y = 0.f; }
    int o = j*BT + t;
    d_V [o] = v;
    d_VX[o] = x * v;
    d_VY[o] = y * v;
}

// ---------------------------------------------------------------------------
// stage1: S0 = V@We, S1 = V@Wo, SU = VX@We + VY@Wo   (contraction over j)
// grid=(4 bt-tiles x64, 8 k-tiles x64, JSPLIT j-splits x64), block=256
// writes JSPLIT partial planes; stage2 sums them while loading.
// ---------------------------------------------------------------------------
__global__ void stage1_kernel(const float* __restrict__ fc1w) {
    __shared__ float Vt [16][64], VXt[16][64], VYt[16][64];
    __shared__ float W0t[16][64], W1t[16][64];
    int bt0 = blockIdx.x * 64;
    int k0  = blockIdx.y * 64;
    int js  = blockIdx.z;
    int jb  = js * 64;
    int t  = threadIdx.x;
    int tx = t & 15;       // k quad
    int ty = t >> 4;       // bt quad
    float s0[4][4], s1[4][4], su[4][4];
    #pragma unroll
    for (int i = 0; i < 4; i++)
        #pragma unroll
        for (int j = 0; j < 4; j++) { s0[i][j]=0.f; s1[i][j]=0.f; su[i][j]=0.f; }

    int lj = t >> 4;           // load row 0..15
    int lc = (t & 15) * 4;     // load col quad

    for (int jc = 0; jc < 64; jc += 16) {
        int jrow = jb + jc + lj;
        *(float4*)&Vt [lj][lc] = *(const float4*)&d_V [jrow*BT + bt0 + lc];
        *(float4*)&VXt[lj][lc] = *(const float4*)&d_VX[jrow*BT + bt0 + lc];
        *(float4*)&VYt[lj][lc] = *(const float4*)&d_VY[jrow*BT + bt0 + lc];
        *(float4*)&W0t[lj][lc] = *(const float4*)&fc1w[(2*jrow  )*KD + k0 + lc];
        *(float4*)&W1t[lj][lc] = *(const float4*)&fc1w[(2*jrow+1)*KD + k0 + lc];
        __syncthreads();
        #pragma unroll
        for (int kk = 0; kk < 16; kk++) {
            float4 v4 = *(const float4*)&Vt [kk][ty*4];
            float4 x4 = *(const float4*)&VXt[kk][ty*4];
            float4 y4 = *(const float4*)&VYt[kk][ty*4];
            float4 w0 = *(const float4*)&W0t[kk][tx*4];
            float4 w1 = *(const float4*)&W1t[kk][tx*4];
            float vv[4] = {v4.x,v4.y,v4.z,v4.w};
            float xx[4] = {x4.x,x4.y,x4.z,x4.w};
            float yy[4] = {y4.x,y4.y,y4.z,y4.w};
            float a0[4] = {w0.x,w0.y,w0.z,w0.w};
            float a1[4] = {w1.x,w1.y,w1.z,w1.w};
            #pragma unroll
            for (int i = 0; i < 4; i++)
                #pragma unroll
                for (int j = 0; j < 4; j++) {
                    s0[i][j] = fmaf(vv[i], a0[j], s0[i][j]);
                    s1[i][j] = fmaf(vv[i], a1[j], s1[i][j]);
                    su[i][j] = fmaf(xx[i], a0[j], fmaf(yy[i], a1[j], su[i][j]));
                }
        }
        __syncthreads();
    }
    float* base = d_S1p + (size_t)js*PSZ;
    #pragma unroll
    for (int i = 0; i < 4; i++) {
        int bt = bt0 + ty*4 + i;
        int k  = k0 + tx*4;
        *(float4*)&base[(0*BT + bt)*KD + k] = make_float4(s0[i][0],s0[i][1],s0[i][2],s0[i][3]);
        *(float4*)&base[(1*BT + bt)*KD + k] = make_float4(s1[i][0],s1[i][1],s1[i][2],s1[i][3]);
        *(float4*)&base[(2*BT + bt)*KD + k] = make_float4(su[i][0],su[i][1],su[i][2],su[i][3]);
    }
}

// ---------------------------------------------------------------------------
// stage2 (fused combine1 + cvec): C (1024 x 768), K = 512, split-K = 2
//   rows    0..767 : A = sum of 4 stage1 partial planes, B = W2_top
//   rows 768..1023 : A = pos, B = W2_bot
// by==0 blocks additionally compute cvec partial = fc1b @ W2_top slice
// (they are the ones staging W2_top) and write d_cvp[bz] (+fcoutb on bz=0).
// grid=(12 n x64, 16 m x64, 2 ksplit), block=128, microtile 8x4
// ---------------------------------------------------------------------------
__global__ void stage2_kernel(const float* __restrict__ fcoutw,
                              const float* __restrict__ pos,
                              const float* __restrict__ fc1b,
                              const float* __restrict__ fcoutb) {
    __shared__ float At[16][64];
    __shared__ float Bt[16][64];
    __shared__ float fb[16];
    int bx = blockIdx.x;           // n tile
    int by = blockIdx.y;           // m tile
    int bz = blockIdx.z;           // k split
    bool isBase = (by >= 12);
    bool doCvec = (by == 0);       // stages W2_top -> correct weights for cvec
    const float* Ap = isBase ? (pos + (by-12)*64*KD) : nullptr;
    const float* Bp = fcoutw + (isBase ? KD*DOUT : 0) + bx*64;
    int t  = threadIdx.x;
    int tx = t & 15;    // 4 cols
    int ty = t >> 4;    // 8 rows
    float acc[8][4];
    #pragma unroll
    for (int i = 0; i < 8; i++)
        #pragma unroll
        for (int j = 0; j < 4; j++) acc[i][j] = 0.f;
    float accC[4] = {0.f, 0.f, 0.f, 0.f};

    int arow = t >> 1;          // 0..63
    int koff = (t & 1) * 8;
    int bk   = t >> 4;          // 0..7 (and +8)
    int bn   = (t & 15) * 4;

    int kend = bz*256 + 256;
    for (int kc = bz*256; kc < kend; kc += 16) {
        float4 a0, a1;
        if (isBase) {
            a0 = *(const float4*)&Ap[arow*KD + kc + koff];
            a1 = *(const float4*)&Ap[arow*KD + kc + koff + 4];
        } else {
            const float* rp = d_S1p + (size_t)(by*64 + arow)*KD + kc + koff;
            float4 q0 = *(const float4*)(rp);
            float4 q1 = *(const float4*)(rp + PSZ);
            float4 q2 = *(const float4*)(rp + 2*PSZ);
            float4 q3 = *(const float4*)(rp + 3*PSZ);
            a0 = make_float4((q0.x+q1.x)+(q2.x+q3.x), (q0.y+q1.y)+(q2.y+q3.y),
                             (q0.z+q1.z)+(q2.z+q3.z), (q0.w+q1.w)+(q2.w+q3.w));
            q0 = *(const float4*)(rp + 4);
            q1 = *(const float4*)(rp + PSZ + 4);
            q2 = *(const float4*)(rp + 2*PSZ + 4);
            q3 = *(const float4*)(rp + 3*PSZ + 4);
            a1 = make_float4((q0.x+q1.x)+(q2.x+q3.x), (q0.y+q1.y)+(q2.y+q3.y),
                             (q0.z+q1.z)+(q2.z+q3.z), (q0.w+q1.w)+(q2.w+q3.w));
        }
        if (doCvec && t < 16) fb[t] = fc1b[kc + t];
        At[koff+0][arow] = a0.x; At[koff+1][arow] = a0.y;
        At[koff+2][arow] = a0.z; At[koff+3][arow] = a0.w;
        At[koff+4][arow] = a1.x; At[koff+5][arow] = a1.y;
        At[koff+6][arow] = a1.z; At[koff+7][arow] = a1.w;
        *(float4*)&Bt[bk  ][bn] = *(const float4*)&Bp[(kc+bk  )*DOUT + bn];
        *(float4*)&Bt[bk+8][bn] = *(const float4*)&Bp[(kc+bk+8)*DOUT + bn];
        __syncthreads();
        #pragma unroll
        for (int kk = 0; kk < 16; kk++) {
            float4 b4 = *(const float4*)&Bt[kk][tx*4];
            float4 aA = *(const float4*)&At[kk][ty*8];
            float4 aB = *(const float4*)&At[kk][ty*8 + 4];
            float av[8] = {aA.x,aA.y,aA.z,aA.w,aB.x,aB.y,aB.z,aB.w};
            float bv[4] = {b4.x,b4.y,b4.z,b4.w};
            if (doCvec) {
                float fbv = fb[kk];
                #pragma unroll
                for (int j = 0; j < 4; j++)
                    accC[j] = fmaf(fbv, bv[j], accC[j]);
            }
            #pragma unroll
            for (int i = 0; i < 8; i++)
                #pragma unroll
                for (int j = 0; j < 4; j++)
                    acc[i][j] = fmaf(av[i], bv[j], acc[i][j]);
        }
        __syncthreads();
    }

    int row0 = by*64 + ty*8;
    int col  = bx*64 + tx*4;
    if (doCvec && ty == 0) {
        if (bz == 0) {
            accC[0] += fcoutb[col];   accC[1] += fcoutb[col+1];
            accC[2] += fcoutb[col+2]; accC[3] += fcoutb[col+3];
        }
        *(float4*)&d_cvp[bz*DOUT + col] =
            make_float4(accC[0], accC[1], accC[2], accC[3]);
    }
    float* outp = d_S2p + (size_t)bz*1024*DOUT;
    #pragma unroll
    for (int i = 0; i < 8; i++)
        *(float4*)&outp[(row0+i)*DOUT + col] =
            make_float4(acc[i][0],acc[i][1],acc[i][2],acc[i][3]);
}

// ---------------------------------------------------------------------------
// epilogue: out[bt,m,o] = VX*A0 + VY*A1 - V*AU + base[m,o] + cvec[o]
// (A*/base are sums of KSPLIT stage2 planes; cvec = sum of KSPLIT cvp planes)
// grid=(32 bt-octets, 8 m-tiles x32), block=192 (one float4 column each)
// ---------------------------------------------------------------------------
#define EPI_BT 8
__global__ void epilogue_kernel(float* __restrict__ out) {
    extern __shared__ float4 sm[];
    float4* A0s = sm;                       // [EPI_BT][192]
    float4* A1s = sm + EPI_BT*192;
    float4* AUs = sm + 2*EPI_BT*192;
    float*  sV  = (float*)(sm + 3*EPI_BT*192);        // [32][EPI_BT]
    float*  sVX = sV  + 32*EPI_BT;
    float*  sVY = sVX + 32*EPI_BT;

    int bt0 = blockIdx.x * EPI_BT;
    int m0  = blockIdx.y * 32;
    int t   = threadIdx.x;     // 0..191

    const float4* p0 = (const float4*)d_S2p;
    const float4* p1 = (const float4*)(d_S2p + (size_t)1024*DOUT);

    #pragma unroll
    for (int i = 0; i < EPI_BT; i++) {
        int r0 = (0*BT + bt0+i)*(DOUT/4) + t;
        int r1 = (1*BT + bt0+i)*(DOUT/4) + t;
        int r2 = (2*BT + bt0+i)*(DOUT/4) + t;
        float4 a = p0[r0], b = p1[r0];
        A0s[i*192+t] = make_float4(a.x+b.x, a.y+b.y, a.z+b.z, a.w+b.w);
        a = p0[r1]; b = p1[r1];
        A1s[i*192+t] = make_float4(a.x+b.x, a.y+b.y, a.z+b.z, a.w+b.w);
        a = p0[r2]; b = p1[r2];
        AUs[i*192+t] = make_float4(a.x+b.x, a.y+b.y, a.z+b.z, a.w+b.w);
    }
    for (int idx = t; idx < 32*EPI_BT; idx += 192) {
        int mm = idx >> 3, bi = idx & 7;
        int src = (m0+mm)*BT + bt0 + bi;
        sV [idx] = d_V [src];
        sVX[idx] = d_VX[src];
        sVY[idx] = d_VY[src];
    }
    // cvec column = sum of KSPLIT cvp planes
    float4 cv;
    {
        const float4* cp = (const float4*)d_cvp;
        float4 c0 = cp[t], c1 = cp[(DOUT/4) + t];
        cv = make_float4(c0.x+c1.x, c0.y+c1.y, c0.z+c1.z, c0.w+c1.w);
    }
    __syncthreads();

    #pragma unroll 2
    for (int mm = 0; mm < 32; mm++) {
        int m = m0 + mm;
        int br = (768 + m)*(DOUT/4) + t;
        float4 b0 = p0[br], b1 = p1[br];
        float4 base = make_float4(b0.x+b1.x+cv.x, b0.y+b1.y+cv.y,
                                  b0.z+b1.z+cv.z, b0.w+b1.w+cv.w);
        #pragma unroll
        for (int i = 0; i < EPI_BT; i++) {
            float v  = sV [mm*EPI_BT+i];
            float vx = sVX[mm*EPI_BT+i];
            float vy = sVY[mm*EPI_BT+i];
            float4 a0 = A0s[i*192+t], a1 = A1s[i*192+t], au = AUs[i*192+t];
            float4 o4;
            o4.x = fmaf(vx, a0.x, fmaf(vy, a1.x, fmaf(-v, au.x, base.x)));
            o4.y = fmaf(vx, a0.y, fmaf(vy, a1.y, fmaf(-v, au.y, base.y)));
            o4.z = fmaf(vx, a0.z, fmaf(vy, a1.z, fmaf(-v, au.z, base.z)));
            o4.w = fmaf(vx, a0.w, fmaf(vy, a1.w, fmaf(-v, au.w, base.w)));
            ((float4*)out)[((bt0+i)*Mm + m)*(DOUT/4) + t] = o4;
        }
    }
}

// ---------------------------------------------------------------------------
extern "C" void kernel_launch(void* const* d_in, const int* in_sizes, int n_in,
                              void* d_out, int out_size) {
    const float* coords = (const float*)d_in[0];
    const float* vis    = (const float*)d_in[1];
    const float* pos    = (const float*)d_in[2];
    const float* fc1w   = (const float*)d_in[3];
    const float* fc1b   = (const float*)d_in[4];
    const float* fcoutw = (const float*)d_in[5];
    const float* fcoutb = (const float*)d_in[6];
    float* out = (float*)d_out;

    static int smem_set = 0;
    int epi_smem = 3*EPI_BT*192*16 + 3*32*EPI_BT*4;   // 76,416 B
    if (!smem_set) {
        cudaFuncSetAttribute(epilogue_kernel,
                             cudaFuncAttributeMaxDynamicSharedMemorySize, epi_smem);
        smem_set = 1;
    }

    prep_kernel    <<<Mm, 256>>>(coords, vis);
    stage1_kernel  <<<dim3(4,8,JSPLIT), 256>>>(fc1w);
    stage2_kernel  <<<dim3(12,16,KSPLIT), 128>>>(fcoutw, pos, fc1b, fcoutb);
    epilogue_kernel<<<dim3(BT/EPI_BT,8), 192, epi_smem>>>(out);
}